// round 14
// baseline (speedup 1.0000x reference)
#include <cuda_runtime.h>

#define WFULL 0xFFFFFFFFu
typedef unsigned long long u64;

// Deterministic fixed-point accumulator (integer adds are associative).
__device__ unsigned long long g_acc = 0ULL;
__device__ unsigned int g_ticket = 0u;

// ---- packed f32x2 helpers (Blackwell sm_103a) ----
__device__ __forceinline__ u64 pk2(float lo, float hi) {
    u64 r; asm("mov.b64 %0,{%1,%2};" : "=l"(r) : "f"(lo), "f"(hi)); return r;
}
__device__ __forceinline__ void unpk2(u64 v, float& lo, float& hi) {
    asm("mov.b64 {%0,%1},%2;" : "=f"(lo), "=f"(hi) : "l"(v));
}
__device__ __forceinline__ u64 fma2(u64 a, u64 b, u64 c) {
    u64 d; asm("fma.rn.f32x2 %0,%1,%2,%3;" : "=l"(d) : "l"(a), "l"(b), "l"(c)); return d;
}
__device__ __forceinline__ u64 mul2(u64 a, u64 b) {
    u64 d; asm("mul.rn.f32x2 %0,%1,%2;" : "=l"(d) : "l"(a), "l"(b)); return d;
}

// One warp per block; each warp processes TWO batch elements packed in f32x2.
// 2 match states per lane over 32 lanes (k = 2*lane, 2*lane+1); lane31 tracks k=64.
__global__ __launch_bounds__(32)
void phmm_pack2_kernel(const int*   __restrict__ x,
                       const float* __restrict__ tp,   // (B,65,7)
                       const float* __restrict__ ep,   // (B,64,4)
                       const float* __restrict__ mus,  // (B,16)
                       const float* __restrict__ lvs,  // (B,16)
                       float* __restrict__ out, int B)
{
    __shared__ float2 es_sm[2][4][32];   // [elem][sym][lane] -> (es state0, es state1)

    const int lane = threadIdx.x;
    int b0 = blockIdx.x * 2, b1 = b0 + 1;
    const bool v0 = (b0 < B), v1 = (b1 < B);
    if (!v0) b0 = B - 1;
    if (!v1) b1 = B - 1;
    const int k0 = lane * 2;

    // ---- transitions (exp once, packed): M2M,M2I,M2D,I2M,I2I,D2M,D2D ----
    const float* a0 = tp + ((size_t)b0 * 65 + k0) * 7;
    const float* a1 = tp + ((size_t)b1 * 65 + k0) * 7;
    const u64 aMM0  = pk2(__expf(a0[0]),  __expf(a1[0]));
    const u64 aMIq0 = pk2(0.25f * __expf(a0[1]), 0.25f * __expf(a1[1]));  // fold log(1/4)
    const u64 aMD0  = pk2(__expf(a0[2]),  __expf(a1[2]));
    const u64 aIM0  = pk2(__expf(a0[3]),  __expf(a1[3]));
    const u64 aIIq0 = pk2(0.25f * __expf(a0[4]), 0.25f * __expf(a1[4]));
    const u64 aDM0  = pk2(__expf(a0[5]),  __expf(a1[5]));
    const u64 dd0   = pk2(__expf(a0[6]),  __expf(a1[6]));
    const u64 aMM1  = pk2(__expf(a0[7]),  __expf(a1[7]));
    const u64 aMIq1 = pk2(0.25f * __expf(a0[8]), 0.25f * __expf(a1[8]));
    const u64 aMD1  = pk2(__expf(a0[9]),  __expf(a1[9]));
    const u64 aIM1  = pk2(__expf(a0[10]), __expf(a1[10]));
    const u64 aIIq1 = pk2(0.25f * __expf(a0[11]), 0.25f * __expf(a1[11]));
    const u64 aDM1  = pk2(__expf(a0[12]), __expf(a1[12]));
    const u64 dd1   = pk2(__expf(a0[13]), __expf(a1[13]));

    u64 aMI64q = 0ULL, aII64q = 0ULL;    // zero on lanes != 31 -> their I64 stays 0
    if (lane == 31) {
        const float* c0p = tp + ((size_t)b0 * 65 + 64) * 7;
        const float* c1p = tp + ((size_t)b1 * 65 + 64) * 7;
        aMI64q = pk2(0.25f * __expf(c0p[1]), 0.25f * __expf(c1p[1]));
        aII64q = pk2(0.25f * __expf(c0p[4]), 0.25f * __expf(c1p[4]));
    }

    // ---- emissions -> per-thread SMEM table (written & read by same thread) ----
    {
        const float4* e40 = (const float4*)(ep + ((size_t)b0 * 64 + k0) * 4);
        const float4* e41 = (const float4*)(ep + ((size_t)b1 * 64 + k0) * 4);
        const float4 fa0 = e40[0], fa1 = e40[1];   // elem0: state0/state1 x 4 syms
        const float4 fb0 = e41[0], fb1 = e41[1];
        es_sm[0][0][lane] = make_float2(__expf(fa0.x), __expf(fa1.x));
        es_sm[0][1][lane] = make_float2(__expf(fa0.y), __expf(fa1.y));
        es_sm[0][2][lane] = make_float2(__expf(fa0.z), __expf(fa1.z));
        es_sm[0][3][lane] = make_float2(__expf(fa0.w), __expf(fa1.w));
        es_sm[1][0][lane] = make_float2(__expf(fb0.x), __expf(fb1.x));
        es_sm[1][1][lane] = make_float2(__expf(fb0.y), __expf(fb1.y));
        es_sm[1][2][lane] = make_float2(__expf(fb0.z), __expf(fb1.z));
        es_sm[1][3][lane] = make_float2(__expf(fb0.w), __expf(fb1.w));
    }

    // ---- symbol streams: 4 symbols per lane, byte-packed, one per element ----
    unsigned xpk0, xpk1;
    {
        const int4 xa = ((const int4*)(x + (size_t)b0 * 128))[lane];
        const int4 xb = ((const int4*)(x + (size_t)b1 * 128))[lane];
        xpk0 = (unsigned)xa.x | ((unsigned)xa.y << 8) | ((unsigned)xa.z << 16) | ((unsigned)xa.w << 24);
        xpk1 = (unsigned)xb.x | ((unsigned)xb.y << 8) | ((unsigned)xb.z << 16) | ((unsigned)xb.w << 24);
    }

    // ---- constant multiplicative scan factors (packed pair-products) ----
    u64 Ds1, Ds2, Ds4, Ds8, Ds16;
    {
        u64 Dc = mul2(dd0, dd1), u;
        Ds1 = Dc; u = __shfl_up_sync(WFULL, Dc, 1);  if (lane >= 1)  Dc = mul2(Dc, u);
        Ds2 = Dc; u = __shfl_up_sync(WFULL, Dc, 2);  if (lane >= 2)  Dc = mul2(Dc, u);
        Ds4 = Dc; u = __shfl_up_sync(WFULL, Dc, 4);  if (lane >= 4)  Dc = mul2(Dc, u);
        Ds8 = Dc; u = __shfl_up_sync(WFULL, Dc, 8);  if (lane >= 8)  Dc = mul2(Dc, u);
        Ds16 = Dc;
    }

    // ---- initial state: fM[0]=1, rest ~0 (exp(-100) ~ 0) ----
    u64 M0 = (lane == 0) ? pk2(1.f, 1.f) : 0ULL;
    u64 M1 = 0ULL, I0 = 0ULL, I1 = 0ULL, M64 = 0ULL, I64 = 0ULL;
    u64 D0, D1, D64;
    {   // initial delete-chain scan
        u64 c0 = mul2(aMD0, M0), c1 = mul2(aMD1, M1);
        u64 C = fma2(dd1, c0, c1), u;
        u = __shfl_up_sync(WFULL, C, 1);  if (lane >= 1)  C = fma2(Ds1, u, C);
        u = __shfl_up_sync(WFULL, C, 2);  if (lane >= 2)  C = fma2(Ds2, u, C);
        u = __shfl_up_sync(WFULL, C, 4);  if (lane >= 4)  C = fma2(Ds4, u, C);
        u = __shfl_up_sync(WFULL, C, 8);  if (lane >= 8)  C = fma2(Ds8, u, C);
        u = __shfl_up_sync(WFULL, C, 16); if (lane >= 16) C = fma2(Ds16, u, C);
        u64 P = __shfl_up_sync(WFULL, C, 1);
        if (lane == 0) P = 0ULL;
        D0 = P; D1 = fma2(dd0, P, c0); D64 = C;
    }

    int ez0 = 0, ez1 = 0;   // exact integer rescale exponents per element

    #pragma unroll 1
    for (int g = 0; g < 32; ++g) {
        const unsigned w0 = __shfl_sync(WFULL, xpk0, g);
        const unsigned w1 = __shfl_sync(WFULL, xpk1, g);

        #pragma unroll
        for (int j = 0; j < 4; ++j) {
            const float2 ea = es_sm[0][(w0 >> (8 * j)) & 3u][lane];
            const float2 eb = es_sm[1][(w1 >> (8 * j)) & 3u][lane];
            const u64 es0 = pk2(ea.x, eb.x);
            const u64 es1 = pk2(ea.y, eb.y);

            const u64 m0 = mul2(es0, fma2(aMM0, M0, fma2(aIM0, I0, mul2(aDM0, D0))));
            const u64 m1 = mul2(es1, fma2(aMM1, M1, fma2(aIM1, I1, mul2(aDM1, D1))));
            const u64 nI64 = fma2(aMI64q, M64, mul2(aII64q, I64));   // OLD M64
            I0 = fma2(aMIq0, M0, mul2(aIIq0, I0));
            I1 = fma2(aMIq1, M1, mul2(aIIq1, I1));
            M64 = m1;            // fM[64] on lane31; harmless elsewhere
            I64 = nI64;
            const u64 sh = __shfl_up_sync(WFULL, m1, 1);
            M0 = (lane == 0) ? 0ULL : sh;   // fM_new[0] = exp(NEG) ~ 0
            M1 = m0;

            // delete-chain scan from NEW fM
            const u64 c0 = mul2(aMD0, M0), c1 = mul2(aMD1, M1);
            u64 C = fma2(dd1, c0, c1), u;
            u = __shfl_up_sync(WFULL, C, 1);  if (lane >= 1)  C = fma2(Ds1, u, C);
            u = __shfl_up_sync(WFULL, C, 2);  if (lane >= 2)  C = fma2(Ds2, u, C);
            u = __shfl_up_sync(WFULL, C, 4);  if (lane >= 4)  C = fma2(Ds4, u, C);
            u = __shfl_up_sync(WFULL, C, 8);  if (lane >= 8)  C = fma2(Ds8, u, C);
            u = __shfl_up_sync(WFULL, C, 16); if (lane >= 16) C = fma2(Ds16, u, C);
            u64 P = __shfl_up_sync(WFULL, C, 1);
            if (lane == 0) P = 0ULL;
            D0 = P; D1 = fma2(dd0, P, c0); D64 = C;
        }

        // ---- power-of-2 rescale once per 4 steps (exact; no MUFU) ----
        float mx0 = 0.f, mx1 = 0.f, ta, tb;
        unpk2(M0, ta, tb);  mx0 = fmaxf(mx0, ta); mx1 = fmaxf(mx1, tb);
        unpk2(M1, ta, tb);  mx0 = fmaxf(mx0, ta); mx1 = fmaxf(mx1, tb);
        unpk2(I0, ta, tb);  mx0 = fmaxf(mx0, ta); mx1 = fmaxf(mx1, tb);
        unpk2(I1, ta, tb);  mx0 = fmaxf(mx0, ta); mx1 = fmaxf(mx1, tb);
        unpk2(M64, ta, tb); mx0 = fmaxf(mx0, ta); mx1 = fmaxf(mx1, tb);
        unpk2(I64, ta, tb); mx0 = fmaxf(mx0, ta); mx1 = fmaxf(mx1, tb);
        #pragma unroll
        for (int k = 16; k >= 1; k >>= 1) {
            mx0 = fmaxf(mx0, __shfl_xor_sync(WFULL, mx0, k));
            mx1 = fmaxf(mx1, __shfl_xor_sync(WFULL, mx1, k));
        }
        const int eb0 = (__float_as_int(mx0) >> 23) - 127;
        const int eb1 = (__float_as_int(mx1) >> 23) - 127;
        ez0 += eb0; ez1 += eb1;
        const u64 sc = pk2(__int_as_float((127 - eb0) << 23),
                           __int_as_float((127 - eb1) << 23));   // exact 2^(-eb)
        M0 = mul2(M0, sc); M1 = mul2(M1, sc);
        I0 = mul2(I0, sc); I1 = mul2(I1, sc);
        D0 = mul2(D0, sc); D1 = mul2(D1, sc);
        M64 = mul2(M64, sc); I64 = mul2(I64, sc); D64 = mul2(D64, sc);
    }

    // ---- KLD: lanes 0..15 -> elem0 dims, lanes 16..31 -> elem1 dims ----
    float kt;
    {
        const int bb = (lane < 16) ? b0 : b1;
        const int dim = lane & 15;
        const float mu = mus[(size_t)bb * 16 + dim];
        const float lv = lvs[(size_t)bb * 16 + dim];
        kt = 1.0f + lv - mu * mu - __expf(lv);
        kt += __shfl_xor_sync(WFULL, kt, 8, 16);
        kt += __shfl_xor_sync(WFULL, kt, 4, 16);
        kt += __shfl_xor_sync(WFULL, kt, 2, 16);
        kt += __shfl_xor_sync(WFULL, kt, 1, 16);
    }
    const float kt0 = __shfl_sync(WFULL, kt, 0);
    const float kt1 = __shfl_sync(WFULL, kt, 16);

    // ---- final + deterministic grid reduction ----
    if (lane == 31) {
        float M64a, M64b, I64a, I64b, D64a, D64b;
        unpk2(M64, M64a, M64b); unpk2(I64, I64a, I64b); unpk2(D64, D64a, D64b);
        const float* f0p = tp + ((size_t)b0 * 65 + 64) * 7;
        const float* f1p = tp + ((size_t)b1 * 65 + 64) * 7;
        float fin0 = fmaf(__expf(f0p[0]), M64a, fmaf(__expf(f0p[3]), I64a, __expf(f0p[5]) * D64a));
        float fin1 = fmaf(__expf(f1p[0]), M64b, fmaf(__expf(f1p[3]), I64b, __expf(f1p[5]) * D64b));
        fin0 = fmaxf(fin0, 1.4e-45f);
        fin1 = fmaxf(fin1, 1.4e-45f);
        const float L2 = 0.69314718055994530942f;
        const float loss0 = -(__logf(fin0) + L2 * (float)ez0) - 0.5f * kt0;
        const float loss1 = -(__logf(fin1) + L2 * (float)ez1) - 0.5f * kt1;
        long long my = (v0 ? llrintf(loss0 * 67108864.0f) : 0LL)
                     + (v1 ? llrintf(loss1 * 67108864.0f) : 0LL);   // fixed point 2^26

        atomicAdd(&g_acc, (unsigned long long)my);
        __threadfence();
        const unsigned int t = atomicAdd(&g_ticket, 1u);
        if (t == gridDim.x - 1) {
            const long long sum = (long long)atomicAdd(&g_acc, 0ULL);
            out[0] = (float)((double)sum / (67108864.0 * (double)B));
            g_acc = 0ULL;     // reset for next graph replay
            g_ticket = 0u;
        }
    }
}

extern "C" void kernel_launch(void* const* d_in, const int* in_sizes, int n_in,
                              void* d_out, int out_size)
{
    const int*   x   = (const int*)d_in[0];
    const float* tp  = (const float*)d_in[1];
    const float* ep  = (const float*)d_in[2];
    const float* mus = (const float*)d_in[3];
    const float* lvs = (const float*)d_in[4];
    float* out = (float*)d_out;

    int B = in_sizes[0] / 128;
    if (B > 4096) B = 4096;
    const int blocks = (B + 1) / 2;   // 2 packed batch elements per 1-warp block

    phmm_pack2_kernel<<<blocks, 32>>>(x, tp, ep, mus, lvs, out, B);
}

// round 17
// speedup vs baseline: 2.0658x; 2.0658x over previous
#include <cuda_runtime.h>

#define WFULL 0xFFFFFFFFu

// Deterministic fixed-point accumulator (integer adds are associative).
__device__ unsigned long long g_acc = 0ULL;
__device__ unsigned int g_ticket = 0u;

// One warp per block; 4 batch elements per warp, each on an 8-lane segment.
// 8 match states per lane: k = 8*s .. 8*s+7 (s = lane&7); s==7 also tracks k=64.
__global__ __launch_bounds__(32)
void phmm8_kernel(const int*   __restrict__ x,
                  const float* __restrict__ tp,   // (B,65,7)
                  const float* __restrict__ ep,   // (B,64,4)
                  const float* __restrict__ mus,  // (B,16)
                  const float* __restrict__ lvs,  // (B,16)
                  float* __restrict__ out, int B)
{
    __shared__ float4 es_lo[4][32];   // [sym][lane]: es for states 0..3 of this lane
    __shared__ float4 es_hi[4][32];   // [sym][lane]: es for states 4..7 of this lane

    const int lane = threadIdx.x;
    const int s    = lane & 7;        // lane within 8-lane segment
    const int e    = lane >> 3;       // element index within warp (0..3)
    int b = blockIdx.x * 4 + e;
    const bool valid = (b < B);
    if (!valid) b = B - 1;            // clamp for safe loads
    const int k0 = s * 8;

    // ---- transitions (exp once): order M2M,M2I,M2D,I2M,I2I,D2M,D2D ----
    const float* a = tp + ((size_t)b * 65 + k0) * 7;
    float aMM[8], aMIq[8], aMD[8], aIM[8], aIIq[8], aDM[8], dd[8];
    #pragma unroll
    for (int j = 0; j < 8; ++j) {
        aMM[j]  = __expf(a[7 * j + 0]);
        aMIq[j] = 0.25f * __expf(a[7 * j + 1]);   // fold LOG_Q = log(1/4)
        aMD[j]  = __expf(a[7 * j + 2]);
        aIM[j]  = __expf(a[7 * j + 3]);
        aIIq[j] = 0.25f * __expf(a[7 * j + 4]);
        aDM[j]  = __expf(a[7 * j + 5]);
        dd[j]   = __expf(a[7 * j + 6]);
    }
    float aMI64q = 0.f, aII64q = 0.f;    // zero on s!=7 -> I64 stays 0 there
    if (s == 7) {
        const float* a64 = tp + ((size_t)b * 65 + 64) * 7;
        aMI64q = 0.25f * __expf(a64[1]);
        aII64q = 0.25f * __expf(a64[4]);
    }

    // In-lane D-chain constants: G = dd1*...*dd7, Gg = G*aMD0.
    const float G  = dd[1] * dd[2] * dd[3] * dd[4] * dd[5] * dd[6] * dd[7];
    const float Gg = G * aMD[0];
    const float Dfull = G * dd[0];     // prod of all 8 dd (segment scan factor base)

    // ---- emissions -> per-thread SMEM tables (written & read by same thread) ----
    {
        const float4* e4 = (const float4*)(ep + ((size_t)b * 64 + k0) * 4);
        float4 er[8];
        #pragma unroll
        for (int j = 0; j < 8; ++j) er[j] = e4[j];   // state j: syms x,y,z,w
        es_lo[0][lane] = make_float4(__expf(er[0].x), __expf(er[1].x), __expf(er[2].x), __expf(er[3].x));
        es_lo[1][lane] = make_float4(__expf(er[0].y), __expf(er[1].y), __expf(er[2].y), __expf(er[3].y));
        es_lo[2][lane] = make_float4(__expf(er[0].z), __expf(er[1].z), __expf(er[2].z), __expf(er[3].z));
        es_lo[3][lane] = make_float4(__expf(er[0].w), __expf(er[1].w), __expf(er[2].w), __expf(er[3].w));
        es_hi[0][lane] = make_float4(__expf(er[4].x), __expf(er[5].x), __expf(er[6].x), __expf(er[7].x));
        es_hi[1][lane] = make_float4(__expf(er[4].y), __expf(er[5].y), __expf(er[6].y), __expf(er[7].y));
        es_hi[2][lane] = make_float4(__expf(er[4].z), __expf(er[5].z), __expf(er[6].z), __expf(er[7].z));
        es_hi[3][lane] = make_float4(__expf(er[4].w), __expf(er[5].w), __expf(er[6].w), __expf(er[7].w));
    }

    // ---- symbol stream: 16 symbols per lane, 2-bit packed ----
    unsigned xpk;
    {
        const int4* x4 = (const int4*)(x + (size_t)b * 128 + s * 16);
        const int4 q0 = x4[0], q1 = x4[1], q2 = x4[2], q3 = x4[3];
        xpk = (unsigned)q0.x | ((unsigned)q0.y << 2) | ((unsigned)q0.z << 4) | ((unsigned)q0.w << 6)
            | ((unsigned)q1.x << 8) | ((unsigned)q1.y << 10) | ((unsigned)q1.z << 12) | ((unsigned)q1.w << 14)
            | ((unsigned)q2.x << 16) | ((unsigned)q2.y << 18) | ((unsigned)q2.z << 20) | ((unsigned)q2.w << 22)
            | ((unsigned)q3.x << 24) | ((unsigned)q3.y << 26) | ((unsigned)q3.z << 28) | ((unsigned)q3.w << 30);
    }

    // ---- segment scan factors (width-8 scan over lane-products) ----
    float Ds1, Ds2, Ds4;
    {
        float Dc = Dfull, u;
        Ds1 = Dc; u = __shfl_up_sync(WFULL, Dc, 1, 8); if (s >= 1) Dc *= u;
        Ds2 = Dc; u = __shfl_up_sync(WFULL, Dc, 2, 8); if (s >= 2) Dc *= u;
        Ds4 = Dc;
    }

    // ---- initial state: fM[0]=1, rest ~0 (exp(-100) ~ 0) ----
    float M[8] = {(s == 0) ? 1.f : 0.f, 0.f, 0.f, 0.f, 0.f, 0.f, 0.f, 0.f};
    float I[8] = {0.f, 0.f, 0.f, 0.f, 0.f, 0.f, 0.f, 0.f};
    float D[8], M64 = 0.f, I64 = 0.f, D64 = 0.f;
    float c_[8];
    {   // initial delete-chain scan
        #pragma unroll
        for (int j = 0; j < 8; ++j) c_[j] = aMD[j] * M[j];
        float T = fmaf(dd[2], c_[1], c_[2]);
        T = fmaf(dd[3], T, c_[3]); T = fmaf(dd[4], T, c_[4]);
        T = fmaf(dd[5], T, c_[5]); T = fmaf(dd[6], T, c_[6]);
        T = fmaf(dd[7], T, c_[7]);
        float C = fmaf(G, c_[0], T), u;
        u = __shfl_up_sync(WFULL, C, 1, 8); if (s >= 1) C = fmaf(Ds1, u, C);
        u = __shfl_up_sync(WFULL, C, 2, 8); if (s >= 2) C = fmaf(Ds2, u, C);
        u = __shfl_up_sync(WFULL, C, 4, 8); if (s >= 4) C = fmaf(Ds4, u, C);
        float P = __shfl_up_sync(WFULL, C, 1, 8);
        if (s == 0) P = 0.f;
        D[0] = P;
        #pragma unroll
        for (int j = 1; j < 8; ++j) D[j] = fmaf(dd[j - 1], D[j - 1], c_[j - 1]);
        D64 = C;
    }

    int ez = 0;   // exact integer accumulator of rescale exponents

    #pragma unroll 1
    for (int g = 0; g < 32; ++g) {
        const unsigned word = __shfl_sync(WFULL, xpk, g >> 2, 8);
        const unsigned bits8 = (word >> (8 * (g & 3))) & 0xFFu;   // 4 syms x 2 bits

        #pragma unroll
        for (int j4 = 0; j4 < 4; ++j4) {
            const int sym = (bits8 >> (2 * j4)) & 3;
            const float4 el = es_lo[sym][lane];
            const float4 eh = es_hi[sym][lane];
            const float es[8] = {el.x, el.y, el.z, el.w, eh.x, eh.y, eh.z, eh.w};

            float m[8];
            #pragma unroll
            for (int j = 0; j < 8; ++j)
                m[j] = es[j] * fmaf(aMM[j], M[j], fmaf(aIM[j], I[j], aDM[j] * D[j]));
            const float nI64 = fmaf(aMI64q, M64, aII64q * I64);   // OLD M64
            #pragma unroll
            for (int j = 0; j < 8; ++j)
                I[j] = fmaf(aMIq[j], M[j], aIIq[j] * I[j]);
            M64 = m[7];          // fM[64] on s==7; harmless elsewhere
            I64 = nI64;

            // partial composite from c1..c7 (independent of the shifted m[7])
            c_[1] = aMD[1] * m[0]; c_[2] = aMD[2] * m[1]; c_[3] = aMD[3] * m[2];
            c_[4] = aMD[4] * m[3]; c_[5] = aMD[5] * m[4]; c_[6] = aMD[6] * m[5];
            c_[7] = aMD[7] * m[6];
            float T = fmaf(dd[2], c_[1], c_[2]);
            T = fmaf(dd[3], T, c_[3]); T = fmaf(dd[4], T, c_[4]);
            T = fmaf(dd[5], T, c_[5]); T = fmaf(dd[6], T, c_[6]);
            T = fmaf(dd[7], T, c_[7]);

            const float sh = __shfl_up_sync(WFULL, m[7], 1, 8);
            M[0] = (s == 0) ? 0.f : sh;    // fM_new[0] = exp(NEG) ~ 0
            M[1] = m[0]; M[2] = m[1]; M[3] = m[2]; M[4] = m[3];
            M[5] = m[4]; M[6] = m[5]; M[7] = m[6];
            c_[0] = aMD[0] * M[0];

            // segment scan (3 levels, width 8); Gg*M[0] completes the composite
            float C = fmaf(Gg, M[0], T), u;
            u = __shfl_up_sync(WFULL, C, 1, 8); if (s >= 1) C = fmaf(Ds1, u, C);
            u = __shfl_up_sync(WFULL, C, 2, 8); if (s >= 2) C = fmaf(Ds2, u, C);
            u = __shfl_up_sync(WFULL, C, 4, 8); if (s >= 4) C = fmaf(Ds4, u, C);
            float P = __shfl_up_sync(WFULL, C, 1, 8);
            if (s == 0) P = 0.f;
            D[0] = P;
            #pragma unroll
            for (int j = 1; j < 8; ++j) D[j] = fmaf(dd[j - 1], D[j - 1], c_[j - 1]);
            D64 = C;
        }

        // ---- power-of-2 rescale once per 4 steps (exact; no MUFU) ----
        float mx = fmaxf(M64, I64);
        #pragma unroll
        for (int j = 0; j < 8; ++j) mx = fmaxf(mx, fmaxf(M[j], I[j]));
        mx = fmaxf(mx, __shfl_xor_sync(WFULL, mx, 4, 8));
        mx = fmaxf(mx, __shfl_xor_sync(WFULL, mx, 2, 8));
        mx = fmaxf(mx, __shfl_xor_sync(WFULL, mx, 1, 8));
        const int eb = (__float_as_int(mx) >> 23) - 127;       // floor(log2 mx)
        const float sc = __int_as_float((127 - eb) << 23);     // exact 2^(-eb)
        ez += eb;
        #pragma unroll
        for (int j = 0; j < 8; ++j) { M[j] *= sc; I[j] *= sc; D[j] *= sc; }
        M64 *= sc; I64 *= sc; D64 *= sc;
    }

    // ---- KLD: 2 latent dims per lane, width-8 reduce ----
    float kt;
    {
        const float2 mu2 = ((const float2*)(mus + (size_t)b * 16))[s];
        const float2 lv2 = ((const float2*)(lvs + (size_t)b * 16))[s];
        kt = (1.0f + lv2.x - mu2.x * mu2.x - __expf(lv2.x))
           + (1.0f + lv2.y - mu2.y * mu2.y - __expf(lv2.y));
        kt += __shfl_xor_sync(WFULL, kt, 4, 8);
        kt += __shfl_xor_sync(WFULL, kt, 2, 8);
        kt += __shfl_xor_sync(WFULL, kt, 1, 8);
    }

    // ---- final loss on s==7 lanes ----
    long long my = 0;
    if (s == 7) {
        const float* a64 = tp + ((size_t)b * 65 + 64) * 7;
        const float aMM64 = __expf(a64[0]);
        const float aIM64 = __expf(a64[3]);
        const float aDM64 = __expf(a64[5]);
        float fin = fmaf(aMM64, M64, fmaf(aIM64, I64, aDM64 * D64));
        fin = fmaxf(fin, 1.4e-45f);
        const float recon = -(__logf(fin) + 0.69314718055994530942f * (float)ez);
        const float loss = recon - 0.5f * kt;
        my = valid ? llrintf(loss * 67108864.0f) : 0LL;   // fixed point 2^26
    }

    // ---- deterministic warp + grid reduction (1 warp per block) ----
    const long long tot = __shfl_sync(WFULL, my, 7)  + __shfl_sync(WFULL, my, 15)
                        + __shfl_sync(WFULL, my, 23) + __shfl_sync(WFULL, my, 31);
    if (lane == 0) {
        atomicAdd(&g_acc, (unsigned long long)tot);
        __threadfence();
        const unsigned int t = atomicAdd(&g_ticket, 1u);
        if (t == gridDim.x - 1) {
            const long long sum = (long long)atomicAdd(&g_acc, 0ULL);
            out[0] = (float)((double)sum / (67108864.0 * (double)B));
            g_acc = 0ULL;     // reset for next graph replay
            g_ticket = 0u;
        }
    }
}

extern "C" void kernel_launch(void* const* d_in, const int* in_sizes, int n_in,
                              void* d_out, int out_size)
{
    const int*   x   = (const int*)d_in[0];
    const float* tp  = (const float*)d_in[1];
    const float* ep  = (const float*)d_in[2];
    const float* mus = (const float*)d_in[3];
    const float* lvs = (const float*)d_in[4];
    float* out = (float*)d_out;

    int B = in_sizes[0] / 128;
    if (B > 4096) B = 4096;
    const int blocks = (B + 3) / 4;   // 4 batch elements per 1-warp block

    phmm8_kernel<<<blocks, 32>>>(x, tp, ep, mus, lvs, out, B);
}